// round 12
// baseline (speedup 1.0000x reference)
#include <cuda_runtime.h>
#include <cstdint>

#define TT    8
#define LL    197
#define HH    12
#define DD    64
#define LK    196
#define NPAIR 112
#define CDIM  768
#define KPAD  224

// attn scratch, packed bf16 (hi,lo) fragment words: [half][q 196][pair 112][224 words]
__device__ uint32_t g_attn2[2u * LK * NPAIR * KPAD];
// zero source for cp.async of invalid rows
__device__ ulonglong2 g_zero4[16];

__device__ __forceinline__ void cp16(uint32_t dst, const void* src) {
    asm volatile("cp.async.cg.shared.global [%0], [%1], 16;" :: "r"(dst), "l"(src));
}
__device__ __forceinline__ float trunc16(float x) {
    return __uint_as_float(__float_as_uint(x) & 0xffff0000u);
}
__device__ __forceinline__ uint32_t packhi(float a, float b) {
    return __byte_perm(__float_as_uint(a), __float_as_uint(b), 0x7632);
}
__device__ __forceinline__ uint32_t packlo(float a, float b) {
    return packhi(a - trunc16(a), b - trunc16(b));
}
__device__ __forceinline__ void mma_bf16(float* c,
    uint32_t a0, uint32_t a1, uint32_t a2, uint32_t a3, uint32_t b0, uint32_t b1)
{
    asm volatile("mma.sync.aligned.m16n8k16.row.col.f32.bf16.bf16.f32 "
        "{%0,%1,%2,%3},{%4,%5,%6,%7},{%8,%9},{%0,%1,%2,%3};"
        : "+f"(c[0]), "+f"(c[1]), "+f"(c[2]), "+f"(c[3])
        : "r"(a0), "r"(a1), "r"(a2), "r"(a3), "r"(b0), "r"(b1));
}
__device__ __forceinline__ void bar_pair(int id) {
    asm volatile("bar.sync %0, 64;" :: "r"(id) : "memory");
}

// ===========================================================================
// Kernel 1: bf16 2-term split scores + softmax(no-max) + head-mean
// grid (4 qtiles of 64, 112 pairs, 2 halves), 256 threads = 8 warps
// warp = (stripe 0..3 [m16], nhalf 0..1 [13 or 12 n-tiles of 8])
// 2 blocks/SM: Q cp.async raw (pitch 88, double buf) -> A-frags in registers;
// K via LDG.128 -> shfl pair -> packed KP (no raw K smem buffer).
// ===========================================================================
#define K1_THREADS 256
#define QROWS 64
#define KROWS 200
#define QPITCH 88
#define QBUF (QROWS * QPITCH)            // 5632 words
#define QR_OFF 0
#define KP_OFF (2 * QBUF)                // 11264
#define RED_OFF (KP_OFF + KROWS * 80)    // 27264
#define SMEM1_WORDS (RED_OFF + 160)      // 27424
#define SMEM1_BYTES (SMEM1_WORDS * 4)    // 109696

__device__ __forceinline__ void k1_load_q(
    const float* __restrict__ q, size_t qbase, int q0,
    int tid, uint32_t smem_u32, int h, int buf)
{
#pragma unroll
    for (int it = 0; it < 4; it++) {
        int i = tid + it * K1_THREADS;
        int row = i >> 4, c4 = i & 15;
        int qg = q0 + row; if (qg > 195) qg = 195;
        const float* src = q + qbase + (size_t)qg * (HH * DD) + h * DD + c4 * 4;
        cp16(smem_u32 + (uint32_t)(QR_OFF + buf * QBUF + row * QPITCH + c4 * 4) * 4, src);
    }
    asm volatile("cp.async.commit_group;");
}

__global__ void __launch_bounds__(K1_THREADS, 2) attn_tc_kernel(
    const float* __restrict__ q, const float* __restrict__ k)
{
    extern __shared__ float sm[];
    uint32_t* smw = (uint32_t*)sm;
    const int tid = threadIdx.x;
    const int lane = tid & 31;
    const int wid = tid >> 5;
    const int stripe = wid >> 1;          // 0..3
    const int nhalf = wid & 1;
    const int laneq = lane >> 2, lane4 = lane & 3;
    const int qt = blockIdx.x;
    const int p = blockIdx.y;
    const int hf = blockIdx.z;
    const int n = p / 7, tp = p % 7;
    const int tq = (hf == 0) ? tp + 1 : tp;
    const int tk = (hf == 0) ? tp : tp + 1;
    const size_t qbase = ((size_t)(n * TT + tq) * LL + 1) * (HH * DD);
    const size_t kbase = ((size_t)(n * TT + tk) * LL + 1) * (HH * DD);
    const int q0 = qt * QROWS;

    uint32_t smem_u32;
    asm("{ .reg .u64 t; cvta.to.shared.u64 t, %1; cvt.u32.u64 %0, t; }"
        : "=r"(smem_u32) : "l"(sm));

    const int nt0 = nhalf ? 13 : 0;
    const int cnt = nhalf ? 12 : 13;
    const int rA = stripe * 16 + laneq;
    const int rB = rA + 8;

    // K convert geometry: 200 rows x 16 float4 units, 256 threads
    const int ku = tid & 15;
    const int kcg = ku >> 2, kw = ku & 3;
    const int kl4out = ((kw & 1) << 1) | (kw >> 1);
    const int kr0 = tid >> 4;             // 0..15, advances by 16
    const float* kcol = k + kbase + ku * 4;

    float macc[13][4];
#pragma unroll
    for (int t = 0; t < 13; t++)
#pragma unroll
        for (int j = 0; j < 4; j++) macc[t][j] = 0.f;

    k1_load_q(q, qbase, q0, tid, smem_u32, 0, 0);
    __syncthreads();   // harmless; aligns blocks

    for (int h = 0; h < HH; h++) {
        const int buf = h & 1;

        // ---- K convert: LDG.128 -> shfl pair -> pack -> STS to KP ----
#pragma unroll
        for (int it = 0; it < 13; it++) {
            int r = kr0 + it * 16;
            if (it < 12 || r < KROWS) {
                int kg = r > 195 ? 195 : r;
                float4 O = *(const float4*)(kcol + (size_t)kg * (HH * DD) + h * DD);
                float4 P;
                P.x = __shfl_xor_sync(0xffffffffu, O.x, 2);
                P.y = __shfl_xor_sync(0xffffffffu, O.y, 2);
                P.z = __shfl_xor_sync(0xffffffffu, O.z, 2);
                P.w = __shfl_xor_sync(0xffffffffu, O.w, 2);
                float f0, f1, f2, f3;
                if (kw & 2) { f0 = P.z; f1 = P.w; f2 = O.z; f3 = O.w; }
                else        { f0 = O.x; f1 = O.y; f2 = P.x; f3 = P.y; }
                uint4 v;
                v.x = packhi(f0, f1);
                v.y = packhi(f2, f3);
                v.z = packlo(f0, f1);
                v.w = packlo(f2, f3);
                *(uint4*)(smw + KP_OFF + r * 80 + kcg * 16 + kl4out * 4) = v;
            }
        }
        if (h + 1 < HH) {
            k1_load_q(q, qbase, q0, tid, smem_u32, h + 1, buf ^ 1);
            asm volatile("cp.async.wait_group 1;");   // Q(h) landed, Q(h+1) flying
        } else {
            asm volatile("cp.async.wait_group 0;");
        }
        __syncthreads();                              // KP(h) + Q(h) visible

        // ---- MMA: A-frags packed in registers from raw Q ----
        float c[13][4];
#pragma unroll
        for (int t = 0; t < 13; t++)
#pragma unroll
            for (int j = 0; j < 4; j++) c[t][j] = 0.f;

        const float* QRb = sm + QR_OFF + buf * QBUF;
#pragma unroll
        for (int kc = 0; kc < 4; kc++) {
            const int qoff = kc * 16 + 2 * lane4;
            float2 qa0 = *(const float2*)(QRb + rA * QPITCH + qoff);
            float2 qa1 = *(const float2*)(QRb + rA * QPITCH + qoff + 8);
            float2 qb0 = *(const float2*)(QRb + rB * QPITCH + qoff);
            float2 qb1 = *(const float2*)(QRb + rB * QPITCH + qoff + 8);
            uint32_t aAx = packhi(qa0.x, qa0.y), aAy = packhi(qa1.x, qa1.y);
            uint32_t aAz = packlo(qa0.x, qa0.y), aAw = packlo(qa1.x, qa1.y);
            uint32_t aBx = packhi(qb0.x, qb0.y), aBy = packhi(qb1.x, qb1.y);
            uint32_t aBz = packlo(qb0.x, qb0.y), aBw = packlo(qb1.x, qb1.y);
#pragma unroll
            for (int t = 0; t < 13; t++) {
                if (t < cnt) {
                    const int brow = (nt0 + t) * 8 + laneq;
                    uint4 bw = *(const uint4*)(smw + KP_OFF + brow * 80 + kc * 16 + lane4 * 4);
                    mma_bf16(c[t], aAx, aBx, aAy, aBy, bw.x, bw.y);
                    mma_bf16(c[t], aAz, aBz, aAw, aBw, bw.x, bw.y);
                    mma_bf16(c[t], aAx, aBx, aAy, aBy, bw.z, bw.w);
                }
            }
        }

        // ---- softmax without max-subtraction ----
        float sA = 0.f, sB = 0.f;
#pragma unroll
        for (int t = 0; t < 13; t++) {
            if (t < cnt) {
                c[t][0] = __expf(c[t][0] * 0.125f);
                c[t][1] = __expf(c[t][1] * 0.125f);
                c[t][2] = __expf(c[t][2] * 0.125f);
                c[t][3] = __expf(c[t][3] * 0.125f);
            }
        }
        if (nhalf && lane4 >= 2) {
            c[11][0] = 0.f; c[11][1] = 0.f; c[11][2] = 0.f; c[11][3] = 0.f;
        }
#pragma unroll
        for (int t = 0; t < 13; t++) {
            if (t < cnt) {
                sA += c[t][0] + c[t][1];
                sB += c[t][2] + c[t][3];
            }
        }
#pragma unroll
        for (int o = 1; o <= 2; o <<= 1) {
            sA += __shfl_xor_sync(0xffffffffu, sA, o);
            sB += __shfl_xor_sync(0xffffffffu, sB, o);
        }
        if (lane4 == 0) {
            sm[RED_OFF + rA * 2 + nhalf] = sA;
            sm[RED_OFF + rB * 2 + nhalf] = sB;
        }
        bar_pair(1 + stripe);
        sA += sm[RED_OFF + rA * 2 + (1 - nhalf)];
        sB += sm[RED_OFF + rB * 2 + (1 - nhalf)];
        const float iA = 1.0f / (12.0f * sA);
        const float iB = 1.0f / (12.0f * sB);
#pragma unroll
        for (int t = 0; t < 13; t++) {
            if (t < cnt) {
                macc[t][0] += c[t][0] * iA;
                macc[t][1] += c[t][1] * iA;
                macc[t][2] += c[t][2] * iB;
                macc[t][3] += c[t][3] * iB;
            }
        }
        __syncthreads();   // KP free for next head's convert; QR(buf) free
    }

    // ---- epilogue: pack mean into bf16 (hi,lo) fragment words -> g_attn2 ----
    uint32_t* stg = smw;   // [64][KPAD] = 14336 words, overlaps QR/KP
    for (int i = tid; i < QROWS * KPAD; i += K1_THREADS) stg[i] = 0u;
    __syncthreads();
#pragma unroll
    for (int t = 0; t < 13; t++) {
        if (t < cnt) {
            const int col0 = (nt0 + t) * 8 + 2 * lane4;
            const int kcg2 = col0 >> 4, rem = col0 & 15;
            const int wp = kcg2 * 16 + ((rem >> 1) & 3) * 4 + (rem >> 3);
            stg[rA * KPAD + wp]     = packhi(macc[t][0], macc[t][1]);
            stg[rA * KPAD + wp + 2] = packlo(macc[t][0], macc[t][1]);
            stg[rB * KPAD + wp]     = packhi(macc[t][2], macc[t][3]);
            stg[rB * KPAD + wp + 2] = packlo(macc[t][2], macc[t][3]);
        }
    }
    __syncthreads();
    for (int i = tid; i < QROWS * 56; i += K1_THREADS) {
        int row = i / 56, s4 = i % 56;
        int qg = q0 + row;
        if (qg < LK) {
            uint4 v = *((const uint4*)(stg + row * KPAD) + s4);
            *((uint4*)(g_attn2 + ((size_t)(hf * LK + qg) * NPAIR + p) * KPAD) + s4) = v;
        }
    }
}

// ===========================================================================
// Kernel 2: out = attn @ Wgather, bf16 2-term split, m16n8k16 (R11)
// grid (6 c-tiles of 128, 196 q), 256 threads = 8 warps (2 mg x 4 ng)
// ===========================================================================
#define K2_THREADS 256
#define A_W 6144
#define WRAW_W 4096
#define A_OFF 0
#define WRAW_OFF (2 * A_W)
#define WP_OFF (WRAW_OFF + 2 * WRAW_W)
#define IDX_OFF (WP_OFF + A_W)
#define SMEM2_BYTES ((IDX_OFF + KPAD) * 4)

__device__ __forceinline__ void k2_load(
    int q, int c0, int tid, uint32_t smem_u32,
    const float* __restrict__ w1, const float* __restrict__ w2,
    const int* __restrict__ idxrow, int s)
{
    const int half = s / 7;
    const int kb = (s % 7) * 32;
    const int buf = s & 1;
#pragma unroll
    for (int t = 0; t < 4; t++) {
        int id = tid + t * K2_THREADS;
        int row = id >> 3, seg = id & 7;
        int nn = row >> 3, tt = row & 7;
        const void* src;
        if (half == 0) {
            src = (tt >= 1) ? (const void*)(g_attn2 +
                    ((size_t)q * NPAIR + nn * 7 + tt - 1) * KPAD + kb + seg * 4)
                            : (const void*)((const char*)g_zero4 + seg * 16);
        } else {
            src = (tt <= 6) ? (const void*)(g_attn2 +
                    ((size_t)(LK + q) * NPAIR + nn * 7 + tt) * KPAD + kb + seg * 4)
                            : (const void*)((const char*)g_zero4 + seg * 16);
        }
        cp16(smem_u32 + (uint32_t)(A_OFF + buf * A_W + row * 48 + seg * 4) * 4, src);
    }
    const float* wb = half ? w2 : w1;
#pragma unroll
    for (int t = 0; t < 4; t++) {
        int id = tid + t * K2_THREADS;
        int kr = id >> 5, seg = id & 31;
        int r = idxrow[kb + kr];
        cp16(smem_u32 + (uint32_t)(WRAW_OFF + buf * WRAW_W + kr * 128 + seg * 4) * 4,
             wb + (size_t)r * CDIM + c0 + seg * 4);
    }
    asm volatile("cp.async.commit_group;");
}

__global__ void __launch_bounds__(K2_THREADS, 2) out_tc_kernel(
    const float* __restrict__ w1, const float* __restrict__ w2,
    const int* __restrict__ idx, float* __restrict__ out)
{
    extern __shared__ uint32_t smw2[];
    int* idxrow = (int*)(smw2 + IDX_OFF);
    const int q = blockIdx.y;
    const int c0 = blockIdx.x * 128;
    const int tid = threadIdx.x;
    const int lane = tid & 31;
    const int wid = tid >> 5;
    const int mg = wid >> 2, ng = wid & 3;
    const int laneq = lane >> 2, lane4 = lane & 3;

    uint32_t smem_u32;
    asm("{ .reg .u64 t; cvta.to.shared.u64 t, %1; cvt.u32.u64 %0, t; }"
        : "=r"(smem_u32) : "l"(smw2));

    const int ccv = tid & 127;
    const int kcjv = tid >> 7;
    float acc[4][4][4];
#pragma unroll
    for (int a = 0; a < 4; a++)
#pragma unroll
        for (int b = 0; b < 4; b++)
#pragma unroll
            for (int d = 0; d < 4; d++) acc[a][b][d] = 0.f;

    for (int i = tid; i < KPAD; i += K2_THREADS)
        idxrow[i] = (i < LK) ? idx[q * LK + i] : 0;
    __syncthreads();

    k2_load(q, c0, tid, smem_u32, w1, w2, idxrow, 0);

    for (int s = 0; s < 14; s++) {
        const int buf = s & 1;
        asm volatile("cp.async.wait_group 0;");
        __syncthreads();
        if (s + 1 < 14) k2_load(q, c0, tid, smem_u32, w1, w2, idxrow, s + 1);

        {
            const float* wr = (const float*)(smw2 + WRAW_OFF + buf * WRAW_W);
#pragma unroll
            for (int t = 0; t < 4; t++) {
                int kcj = kcjv + t * 2;
                int ckc = kcj >> 2, cj = kcj & 3;
                int k0 = ckc * 16 + 2 * cj;
                float f0 = wr[k0 * 128 + ccv];
                float f1 = wr[(k0 + 1) * 128 + ccv];
                float f2 = wr[(k0 + 8) * 128 + ccv];
                float f3 = wr[(k0 + 9) * 128 + ccv];
                uint4 v;
                v.x = packhi(f0, f1);
                v.y = packhi(f2, f3);
                v.z = packlo(f0, f1);
                v.w = packlo(f2, f3);
                *(uint4*)(smw2 + WP_OFF + ccv * 48 + ckc * 16 + cj * 4) = v;
            }
        }
        __syncthreads();

        const uint32_t* Ab = smw2 + A_OFF + buf * A_W + (mg * 64 + laneq) * 48 + lane4 * 4;
        const uint32_t* Bb = smw2 + WP_OFF + (ng * 32 + laneq) * 48 + lane4 * 4;
#pragma unroll
        for (int kc = 0; kc < 2; kc++) {
            uint4 bw[4];
#pragma unroll
            for (int nt = 0; nt < 4; nt++)
                bw[nt] = *(const uint4*)(Bb + nt * 8 * 48 + kc * 16);
#pragma unroll
            for (int mt = 0; mt < 4; mt++) {
                uint4 a0 = *(const uint4*)(Ab + mt * 16 * 48 + kc * 16);
                uint4 a1 = *(const uint4*)(Ab + (mt * 16 + 8) * 48 + kc * 16);
#pragma unroll
                for (int nt = 0; nt < 4; nt++) {
                    mma_bf16(acc[mt][nt], a0.x, a1.x, a0.y, a1.y, bw[nt].x, bw[nt].y);
                    mma_bf16(acc[mt][nt], a0.z, a1.z, a0.w, a1.w, bw[nt].x, bw[nt].y);
                    mma_bf16(acc[mt][nt], a0.x, a1.x, a0.y, a1.y, bw[nt].z, bw[nt].w);
                }
            }
        }
    }

#pragma unroll
    for (int mt = 0; mt < 4; mt++) {
#pragma unroll
        for (int nt = 0; nt < 4; nt++) {
            int mrow = mg * 64 + mt * 16 + laneq;
            int col = c0 + ng * 32 + nt * 8 + 2 * lane4;
            float* ob0 = out + ((size_t)mrow * LL + q + 1) * CDIM + col;
            float* ob1 = out + ((size_t)(mrow + 8) * LL + q + 1) * CDIM + col;
            *(float2*)ob0 = make_float2(acc[mt][nt][0], acc[mt][nt][1]);
            *(float2*)ob1 = make_float2(acc[mt][nt][2], acc[mt][nt][3]);
        }
    }
}

__global__ void zero_l0_kernel(float* __restrict__ out) {
    int i = blockIdx.x * blockDim.x + threadIdx.x;
    int nt = i / CDIM, cc = i - nt * CDIM;
    out[(size_t)nt * LL * CDIM + cc] = 0.f;
}

extern "C" void kernel_launch(void* const* d_in, const int* in_sizes, int n_in,
                              void* d_out, int out_size)
{
    const float* q  = (const float*)d_in[0];
    const float* k  = (const float*)d_in[1];
    const float* w1 = (const float*)d_in[2];
    const float* w2 = (const float*)d_in[3];
    const int*  idx = (const int*)d_in[4];
    float* out = (float*)d_out;

    cudaFuncSetAttribute(attn_tc_kernel, cudaFuncAttributeMaxDynamicSharedMemorySize, SMEM1_BYTES);
    cudaFuncSetAttribute(out_tc_kernel, cudaFuncAttributeMaxDynamicSharedMemorySize, SMEM2_BYTES);

    attn_tc_kernel<<<dim3(4, NPAIR, 2), K1_THREADS, SMEM1_BYTES>>>(q, k);
    zero_l0_kernel<<<96, 1024>>>(out);
    out_tc_kernel<<<dim3(6, LK), K2_THREADS, SMEM2_BYTES>>>(w1, w2, idx, out);
}

// round 13
// speedup vs baseline: 1.1392x; 1.1392x over previous
#include <cuda_runtime.h>
#include <cstdint>

#define TT    8
#define LL    197
#define HH    12
#define DD    64
#define LK    196
#define NPAIR 112
#define CDIM  768
#define KPAD  224

// attn scratch, packed bf16 (hi,lo) fragment words: [half][q 196][pair 112][224 words]
__device__ uint32_t g_attn2[2u * LK * NPAIR * KPAD];
// zero source for cp.async of invalid rows
__device__ ulonglong2 g_zero4[16];

__device__ __forceinline__ void cp16(uint32_t dst, const void* src) {
    asm volatile("cp.async.cg.shared.global [%0], [%1], 16;" :: "r"(dst), "l"(src));
}
__device__ __forceinline__ float trunc16(float x) {
    return __uint_as_float(__float_as_uint(x) & 0xffff0000u);
}
__device__ __forceinline__ uint32_t packhi(float a, float b) {
    return __byte_perm(__float_as_uint(a), __float_as_uint(b), 0x7632);
}
__device__ __forceinline__ uint32_t packlo(float a, float b) {
    return packhi(a - trunc16(a), b - trunc16(b));
}
__device__ __forceinline__ void mma_bf16(float* c,
    uint32_t a0, uint32_t a1, uint32_t a2, uint32_t a3, uint32_t b0, uint32_t b1)
{
    asm volatile("mma.sync.aligned.m16n8k16.row.col.f32.bf16.bf16.f32 "
        "{%0,%1,%2,%3},{%4,%5,%6,%7},{%8,%9},{%0,%1,%2,%3};"
        : "+f"(c[0]), "+f"(c[1]), "+f"(c[2]), "+f"(c[3])
        : "r"(a0), "r"(a1), "r"(a2), "r"(a3), "r"(b0), "r"(b1));
}
__device__ __forceinline__ void bar_pair(int id) {
    asm volatile("bar.sync %0, 64;" :: "r"(id) : "memory");
}

// ===========================================================================
// Kernel 1: bf16 2-term split scores + softmax(no-max) + head-mean (R11, proven)
// grid (2 qtiles, 112 pairs, 2 halves), 448 threads = 14 warps
// ===========================================================================
#define K1_THREADS 448
#define QROWS 112
#define KROWS 200
#define QPITCH 88
#define QBUF (QROWS * QPITCH)            // 9856 words
#define QR_OFF 0
#define KR_OFF (2 * QBUF)                // 19712
#define KP_OFF (KR_OFF + KROWS * 64)     // 32512
#define RED_OFF (KP_OFF + KROWS * 80)    // 48512
#define SMEM1_WORDS (RED_OFF + 224)      // 48736
#define SMEM1_BYTES (SMEM1_WORDS * 4)    // 194944

__device__ __forceinline__ void k1_load_q(
    const float* __restrict__ q, size_t qbase, int q0,
    int tid, uint32_t smem_u32, int h, int buf)
{
#pragma unroll
    for (int it = 0; it < 4; it++) {
        int i = tid + it * K1_THREADS;
        int row = i >> 4, c4 = i & 15;
        int qg = q0 + row; if (qg > 195) qg = 195;
        const float* src = q + qbase + (size_t)qg * (HH * DD) + h * DD + c4 * 4;
        cp16(smem_u32 + (uint32_t)(QR_OFF + buf * QBUF + row * QPITCH + c4 * 4) * 4, src);
    }
    asm volatile("cp.async.commit_group;");
}

__global__ void __launch_bounds__(K1_THREADS, 1) attn_tc_kernel(
    const float* __restrict__ q, const float* __restrict__ k)
{
    extern __shared__ float sm[];
    uint32_t* smw = (uint32_t*)sm;
    const int tid = threadIdx.x;
    const int lane = tid & 31;
    const int wid = tid >> 5;
    const int stripe = wid >> 1;
    const int nhalf = wid & 1;
    const int laneq = lane >> 2, lane4 = lane & 3;
    const int qt = blockIdx.x;
    const int p = blockIdx.y;
    const int hf = blockIdx.z;
    const int n = p / 7, tp = p % 7;
    const int tq = (hf == 0) ? tp + 1 : tp;
    const int tk = (hf == 0) ? tp : tp + 1;
    const size_t qbase = ((size_t)(n * TT + tq) * LL + 1) * (HH * DD);
    const size_t kbase = ((size_t)(n * TT + tk) * LL + 1) * (HH * DD);
    const int q0 = qt * QROWS;

    uint32_t smem_u32;
    asm("{ .reg .u64 t; cvta.to.shared.u64 t, %1; cvt.u32.u64 %0, t; }"
        : "=r"(smem_u32) : "l"(sm));

    const int nt0 = nhalf ? 13 : 0;
    const int cnt = nhalf ? 12 : 13;
    const int rA = stripe * 16 + laneq;
    const int rB = rA + 8;

    const int ku = tid & 15;
    const int kcg = ku >> 2, kw = ku & 3;
    const int kl4out = ((kw & 1) << 1) | (kw >> 1);
    const int kr0 = tid >> 4;

    float macc[13][4];
#pragma unroll
    for (int t = 0; t < 13; t++)
#pragma unroll
        for (int j = 0; j < 4; j++) macc[t][j] = 0.f;

#pragma unroll
    for (int it = 0; it < 8; it++) {
        if (it < 7 || tid < 64) {
            int r = kr0 + it * 28;
            int kg = r > 195 ? 195 : r;
            cp16(smem_u32 + (uint32_t)(KR_OFF + r * 64 + ku * 4) * 4,
                 k + kbase + (size_t)kg * (HH * DD) + 0 * DD + ku * 4);
        }
    }
    asm volatile("cp.async.commit_group;");
    k1_load_q(q, qbase, q0, tid, smem_u32, 0, 0);

    for (int h = 0; h < HH; h++) {
        const int buf = h & 1;
        asm volatile("cp.async.wait_group 0;");

#pragma unroll
        for (int it = 0; it < 8; it++) {
            if (it < 7 || tid < 64) {
                int r = kr0 + it * 28;
                float4 O = *(const float4*)(sm + KR_OFF + r * 64 + ku * 4);
                float4 P;
                P.x = __shfl_xor_sync(0xffffffffu, O.x, 2);
                P.y = __shfl_xor_sync(0xffffffffu, O.y, 2);
                P.z = __shfl_xor_sync(0xffffffffu, O.z, 2);
                P.w = __shfl_xor_sync(0xffffffffu, O.w, 2);
                float f0, f1, f2, f3;
                if (kw & 2) { f0 = P.z; f1 = P.w; f2 = O.z; f3 = O.w; }
                else        { f0 = O.x; f1 = O.y; f2 = P.x; f3 = P.y; }
                uint4 v;
                v.x = packhi(f0, f1);
                v.y = packhi(f2, f3);
                v.z = packlo(f0, f1);
                v.w = packlo(f2, f3);
                *(uint4*)(smw + KP_OFF + r * 80 + kcg * 16 + kl4out * 4) = v;
                if (h + 1 < HH) {
                    int kg = r > 195 ? 195 : r;
                    cp16(smem_u32 + (uint32_t)(KR_OFF + r * 64 + ku * 4) * 4,
                         k + kbase + (size_t)kg * (HH * DD) + (h + 1) * DD + ku * 4);
                }
            }
        }
        asm volatile("cp.async.commit_group;");
        if (h + 1 < HH) k1_load_q(q, qbase, q0, tid, smem_u32, h + 1, buf ^ 1);
        __syncthreads();

        float c[13][4];
#pragma unroll
        for (int t = 0; t < 13; t++)
#pragma unroll
            for (int j = 0; j < 4; j++) c[t][j] = 0.f;

        const float* QRb = sm + QR_OFF + buf * QBUF;
#pragma unroll
        for (int kc = 0; kc < 4; kc++) {
            const int qoff = kc * 16 + 2 * lane4;
            float2 qa0 = *(const float2*)(QRb + rA * QPITCH + qoff);
            float2 qa1 = *(const float2*)(QRb + rA * QPITCH + qoff + 8);
            float2 qb0 = *(const float2*)(QRb + rB * QPITCH + qoff);
            float2 qb1 = *(const float2*)(QRb + rB * QPITCH + qoff + 8);
            uint32_t aAx = packhi(qa0.x, qa0.y), aAy = packhi(qa1.x, qa1.y);
            uint32_t aAz = packlo(qa0.x, qa0.y), aAw = packlo(qa1.x, qa1.y);
            uint32_t aBx = packhi(qb0.x, qb0.y), aBy = packhi(qb1.x, qb1.y);
            uint32_t aBz = packlo(qb0.x, qb0.y), aBw = packlo(qb1.x, qb1.y);
#pragma unroll
            for (int t = 0; t < 13; t++) {
                if (t < cnt) {
                    const int brow = (nt0 + t) * 8 + laneq;
                    uint4 bw = *(const uint4*)(smw + KP_OFF + brow * 80 + kc * 16 + lane4 * 4);
                    mma_bf16(c[t], aAx, aBx, aAy, aBy, bw.x, bw.y);
                    mma_bf16(c[t], aAz, aBz, aAw, aBw, bw.x, bw.y);
                    mma_bf16(c[t], aAx, aBx, aAy, aBy, bw.z, bw.w);
                }
            }
        }

        float sA = 0.f, sB = 0.f;
#pragma unroll
        for (int t = 0; t < 13; t++) {
            if (t < cnt) {
                c[t][0] = __expf(c[t][0] * 0.125f);
                c[t][1] = __expf(c[t][1] * 0.125f);
                c[t][2] = __expf(c[t][2] * 0.125f);
                c[t][3] = __expf(c[t][3] * 0.125f);
            }
        }
        if (nhalf && lane4 >= 2) {
            c[11][0] = 0.f; c[11][1] = 0.f; c[11][2] = 0.f; c[11][3] = 0.f;
        }
#pragma unroll
        for (int t = 0; t < 13; t++) {
            if (t < cnt) {
                sA += c[t][0] + c[t][1];
                sB += c[t][2] + c[t][3];
            }
        }
#pragma unroll
        for (int o = 1; o <= 2; o <<= 1) {
            sA += __shfl_xor_sync(0xffffffffu, sA, o);
            sB += __shfl_xor_sync(0xffffffffu, sB, o);
        }
        if (lane4 == 0) {
            sm[RED_OFF + rA * 2 + nhalf] = sA;
            sm[RED_OFF + rB * 2 + nhalf] = sB;
        }
        bar_pair(1 + stripe);
        sA += sm[RED_OFF + rA * 2 + (1 - nhalf)];
        sB += sm[RED_OFF + rB * 2 + (1 - nhalf)];
        const float iA = 1.0f / (12.0f * sA);
        const float iB = 1.0f / (12.0f * sB);
#pragma unroll
        for (int t = 0; t < 13; t++) {
            if (t < cnt) {
                macc[t][0] += c[t][0] * iA;
                macc[t][1] += c[t][1] * iA;
                macc[t][2] += c[t][2] * iB;
                macc[t][3] += c[t][3] * iB;
            }
        }
        __syncthreads();
    }

    uint32_t* stg = smw;
    for (int i = tid; i < QROWS * KPAD; i += K1_THREADS) stg[i] = 0u;
    __syncthreads();
#pragma unroll
    for (int t = 0; t < 13; t++) {
        if (t < cnt) {
            const int col0 = (nt0 + t) * 8 + 2 * lane4;
            const int kcg2 = col0 >> 4, rem = col0 & 15;
            const int wp = kcg2 * 16 + ((rem >> 1) & 3) * 4 + (rem >> 3);
            stg[rA * KPAD + wp]     = packhi(macc[t][0], macc[t][1]);
            stg[rA * KPAD + wp + 2] = packlo(macc[t][0], macc[t][1]);
            stg[rB * KPAD + wp]     = packhi(macc[t][2], macc[t][3]);
            stg[rB * KPAD + wp + 2] = packlo(macc[t][2], macc[t][3]);
        }
    }
    __syncthreads();
    for (int i = tid; i < QROWS * 56; i += K1_THREADS) {
        int row = i / 56, s4 = i % 56;
        int qg = q0 + row;
        if (qg < LK) {
            uint4 v = *((const uint4*)(stg + row * KPAD) + s4);
            *((uint4*)(g_attn2 + ((size_t)(hf * LK + qg) * NPAIR + p) * KPAD) + s4) = v;
        }
    }
}

// ===========================================================================
// Kernel 2: out = attn @ Wgather, bf16 2-term split, m16n8k16
// grid (6 c-tiles of 128, 196 q), 256 threads = 8 warps (2 mg x 4 ng)
// NEW: B-fragments built IN REGISTERS from raw W (pitch 132, conflict-free
// scattered LDS.32) -> no WP buffer, ONE block barrier per iteration.
// smem words: A 2x6144 | Wraw 2x(32x132)=8448 | idx 224  -> ~84 KB, 2 blk/SM
// ===========================================================================
#define K2_THREADS 256
#define A_W 6144
#define WR_PITCH 132
#define WRAW_W (32 * WR_PITCH)           // 4224 words
#define A_OFF 0
#define WRAW_OFF (2 * A_W)               // 12288
#define IDX_OFF (WRAW_OFF + 2 * WRAW_W)  // 20736
#define SMEM2_BYTES ((IDX_OFF + KPAD) * 4)   // 83840

__device__ __forceinline__ void k2_load(
    int q, int c0, int tid, uint32_t smem_u32,
    const float* __restrict__ w1, const float* __restrict__ w2,
    const int* __restrict__ idxrow, int s)
{
    const int half = s / 7;
    const int kb = (s % 7) * 32;
    const int buf = s & 1;
    // A: 128 rows x 8 cp16 (packed fragment words straight from g_attn2)
#pragma unroll
    for (int t = 0; t < 4; t++) {
        int id = tid + t * K2_THREADS;
        int row = id >> 3, seg = id & 7;
        int nn = row >> 3, tt = row & 7;
        const void* src;
        if (half == 0) {
            src = (tt >= 1) ? (const void*)(g_attn2 +
                    ((size_t)q * NPAIR + nn * 7 + tt - 1) * KPAD + kb + seg * 4)
                            : (const void*)((const char*)g_zero4 + seg * 16);
        } else {
            src = (tt <= 6) ? (const void*)(g_attn2 +
                    ((size_t)(LK + q) * NPAIR + nn * 7 + tt) * KPAD + kb + seg * 4)
                            : (const void*)((const char*)g_zero4 + seg * 16);
        }
        cp16(smem_u32 + (uint32_t)(A_OFF + buf * A_W + row * 48 + seg * 4) * 4, src);
    }
    // W raw: 32 gathered rows x 32 cp16, pitch 132 floats
    const float* wb = half ? w2 : w1;
#pragma unroll
    for (int t = 0; t < 4; t++) {
        int id = tid + t * K2_THREADS;
        int kr = id >> 5, seg = id & 31;
        int r = idxrow[kb + kr];
        cp16(smem_u32 + (uint32_t)(WRAW_OFF + buf * WRAW_W + kr * WR_PITCH + seg * 4) * 4,
             wb + (size_t)r * CDIM + c0 + seg * 4);
    }
    asm volatile("cp.async.commit_group;");
}

__global__ void __launch_bounds__(K2_THREADS, 2) out_tc_kernel(
    const float* __restrict__ w1, const float* __restrict__ w2,
    const int* __restrict__ idx, float* __restrict__ out)
{
    extern __shared__ uint32_t smw2[];
    int* idxrow = (int*)(smw2 + IDX_OFF);
    const int q = blockIdx.y;
    const int c0 = blockIdx.x * 128;
    const int tid = threadIdx.x;
    const int lane = tid & 31;
    const int wid = tid >> 5;
    const int mg = wid >> 2, ng = wid & 3;
    const int laneq = lane >> 2, lane4 = lane & 3;

    uint32_t smem_u32;
    asm("{ .reg .u64 t; cvta.to.shared.u64 t, %1; cvt.u32.u64 %0, t; }"
        : "=r"(smem_u32) : "l"(smw2));

    float acc[4][4][4];
#pragma unroll
    for (int a = 0; a < 4; a++)
#pragma unroll
        for (int b = 0; b < 4; b++)
#pragma unroll
            for (int d = 0; d < 4; d++) acc[a][b][d] = 0.f;

    for (int i = tid; i < KPAD; i += K2_THREADS)
        idxrow[i] = (i < LK) ? idx[q * LK + i] : 0;
    __syncthreads();

    k2_load(q, c0, tid, smem_u32, w1, w2, idxrow, 0);

    // B-frag source geometry: c column for this lane per nt
    // c_nt = ng*32 + nt*8 + laneq ; k0 = kc*16 + 2*lane4
    const int cbase = ng * 32 + laneq;

    for (int s = 0; s < 14; s++) {
        const int buf = s & 1;
        asm volatile("cp.async.wait_group 0;");    // cp(s) landed (own thread)
        __syncthreads();                           // visible to all; MMA(s-1) done
        if (s + 1 < 14) k2_load(q, c0, tid, smem_u32, w1, w2, idxrow, s + 1);

        const float* wr = (const float*)(smw2 + WRAW_OFF + buf * WRAW_W);
        const uint32_t* Ab = smw2 + A_OFF + buf * A_W + (mg * 64 + laneq) * 48 + lane4 * 4;
#pragma unroll
        for (int kc = 0; kc < 2; kc++) {
            const int k0 = kc * 16 + 2 * lane4;
            const float* w0 = wr + k0 * WR_PITCH + cbase;
            uint4 bw[4];
#pragma unroll
            for (int nt = 0; nt < 4; nt++) {
                float f0 = w0[nt * 8];
                float f1 = w0[WR_PITCH + nt * 8];
                float f2 = w0[8 * WR_PITCH + nt * 8];
                float f3 = w0[9 * WR_PITCH + nt * 8];
                bw[nt].x = packhi(f0, f1);
                bw[nt].y = packhi(f2, f3);
                bw[nt].z = packlo(f0, f1);
                bw[nt].w = packlo(f2, f3);
            }
#pragma unroll
            for (int mt = 0; mt < 4; mt++) {
                uint4 a0 = *(const uint4*)(Ab + mt * 16 * 48 + kc * 16);
                uint4 a1 = *(const uint4*)(Ab + (mt * 16 + 8) * 48 + kc * 16);
#pragma unroll
                for (int nt = 0; nt < 4; nt++) {
                    mma_bf16(acc[mt][nt], a0.x, a1.x, a0.y, a1.y, bw[nt].x, bw[nt].y);
                    mma_bf16(acc[mt][nt], a0.z, a1.z, a0.w, a1.w, bw[nt].x, bw[nt].y);
                    mma_bf16(acc[mt][nt], a0.x, a1.x, a0.y, a1.y, bw[nt].z, bw[nt].w);
                }
            }
        }
    }

#pragma unroll
    for (int mt = 0; mt < 4; mt++) {
#pragma unroll
        for (int nt = 0; nt < 4; nt++) {
            int mrow = mg * 64 + mt * 16 + laneq;
            int col = c0 + ng * 32 + nt * 8 + 2 * lane4;
            float* ob0 = out + ((size_t)mrow * LL + q + 1) * CDIM + col;
            float* ob1 = out + ((size_t)(mrow + 8) * LL + q + 1) * CDIM + col;
            *(float2*)ob0 = make_float2(acc[mt][nt][0], acc[mt][nt][1]);
            *(float2*)ob1 = make_float2(acc[mt][nt][2], acc[mt][nt][3]);
        }
    }
}

__global__ void zero_l0_kernel(float* __restrict__ out) {
    int i = blockIdx.x * blockDim.x + threadIdx.x;
    int nt = i / CDIM, cc = i - nt * CDIM;
    out[(size_t)nt * LL * CDIM + cc] = 0.f;
}

extern "C" void kernel_launch(void* const* d_in, const int* in_sizes, int n_in,
                              void* d_out, int out_size)
{
    const float* q  = (const float*)d_in[0];
    const float* k  = (const float*)d_in[1];
    const float* w1 = (const float*)d_in[2];
    const float* w2 = (const float*)d_in[3];
    const int*  idx = (const int*)d_in[4];
    float* out = (float*)d_out;

    cudaFuncSetAttribute(attn_tc_kernel, cudaFuncAttributeMaxDynamicSharedMemorySize, SMEM1_BYTES);
    cudaFuncSetAttribute(out_tc_kernel, cudaFuncAttributeMaxDynamicSharedMemorySize, SMEM2_BYTES);

    attn_tc_kernel<<<dim3(2, NPAIR, 2), K1_THREADS, SMEM1_BYTES>>>(q, k);
    zero_l0_kernel<<<96, 1024>>>(out);
    out_tc_kernel<<<dim3(6, LK), K2_THREADS, SMEM2_BYTES>>>(w1, w2, idx, out);
}